// round 1
// baseline (speedup 1.0000x reference)
#include <cuda_runtime.h>
#include <cstdint>
#include <math.h>

#define NB 4
#define SS 2048
#define DD 1024
#define NEGV (-1e10f)

// Scratch (device globals: allocation-free per harness rules)
__device__ float g_q[NB * SS * DD];                 // 33.5 MB
__device__ float g_k[NB * SS * DD];
__device__ float g_v[NB * SS * DD];
__device__ float g_p[(size_t)NB * SS * SS];         // 64 MB scores/probs

// ---------------------------------------------------------------------------
// packed f32x2 helpers (FFMA2 path — only reachable via PTX fma.rn.f32x2)
// ---------------------------------------------------------------------------
__device__ __forceinline__ unsigned long long fma2(unsigned long long a,
                                                   unsigned long long b,
                                                   unsigned long long c) {
    unsigned long long d;
    asm("fma.rn.f32x2 %0, %1, %2, %3;" : "=l"(d) : "l"(a), "l"(b), "l"(c));
    return d;
}

__device__ __forceinline__ unsigned long long bcast2(float x) {
    unsigned long long r;
    asm("mov.b64 %0, {%1, %1};" : "=l"(r) : "r"(__float_as_uint(x)));
    return r;
}

// ---------------------------------------------------------------------------
// One GEMM template, 5 modes:
//   0/1/2 : proj q/k/v : C[m,e] = sum_d A[m,d]*W[e,d] + bias[e]   (NT)
//   3     : scores     : P[q,k] = (q.k)/32, mask-replace, causal-add (NT)
//   4     : PV         : O[q,d] = sum_k P[q,k]*V[k,d]             (NN)
// Tiles: 128x128x8, 256 threads, 8x8 microtile, f32x2 packed FMA.
// All dims divide evenly — no bounds checks.
// ---------------------------------------------------------------------------
template <int MODE>
__global__ __launch_bounds__(256) void gemm_kernel(
    const float* __restrict__ extA, const float* __restrict__ extB,
    const float* __restrict__ auxf, const int* __restrict__ auxi,
    float* __restrict__ extC)
{
    constexpr int K     = (MODE == 4) ? SS : DD;     // contraction length
    constexpr int NCOLS = (MODE == 3) ? SS : DD;     // ld of C (and of B for NN)

    const int bz = blockIdx.z;

    const float* A;
    const float* Bm;
    float* C;
    if (MODE == 0)      { A = extA; Bm = extB; C = g_q; }
    else if (MODE == 1) { A = extA; Bm = extB; C = g_k; }
    else if (MODE == 2) { A = extA; Bm = extB; C = g_v; }
    else if (MODE == 3) {
        A  = g_q + (size_t)bz * SS * DD;
        Bm = g_k + (size_t)bz * SS * DD;
        C  = g_p + (size_t)bz * SS * SS;
    } else {
        A  = g_p + (size_t)bz * SS * SS;
        Bm = g_v + (size_t)bz * SS * DD;
        C  = extC + (size_t)bz * SS * DD;
    }

    __shared__ float As[8][128];
    __shared__ float Bs[8][128];

    const int tid = threadIdx.x;
    const int tx  = tid & 15;        // 0..15 -> n microtile
    const int ty  = tid >> 4;        // 0..15 -> m microtile
    const int m0  = blockIdx.y * 128;
    const int n0  = blockIdx.x * 128;

    // global-load mapping
    const int aRow = tid >> 1;             // 0..127
    const int aCol = (tid & 1) << 2;       // 0 or 4
    const int bRow = tid >> 5;             // 0..7   (NN)
    const int bCol = (tid & 31) << 2;      // 0..124 (NN)

    const float* Ap = A + (size_t)(m0 + aRow) * K + aCol;
    const float* Bp;
    if (MODE != 4) Bp = Bm + (size_t)(n0 + aRow) * K + aCol;          // NT: B is [N x K]
    else           Bp = Bm + (size_t)bRow * NCOLS + (n0 + bCol);      // NN: B is [K x N]

    unsigned long long acc[8][4];
    #pragma unroll
    for (int i = 0; i < 8; i++)
        #pragma unroll
        for (int j = 0; j < 4; j++) acc[i][j] = 0ull;

    // register prefetch of first tile
    float4 av = *(const float4*)Ap;
    float4 bv = *(const float4*)Bp;

    for (int k0 = 0; k0 < K; k0 += 8) {
        // stage into smem (A transposed to [k][m]; NT-B transposed to [k][n])
        As[aCol + 0][aRow] = av.x; As[aCol + 1][aRow] = av.y;
        As[aCol + 2][aRow] = av.z; As[aCol + 3][aRow] = av.w;
        if (MODE != 4) {
            Bs[aCol + 0][aRow] = bv.x; Bs[aCol + 1][aRow] = bv.y;
            Bs[aCol + 2][aRow] = bv.z; Bs[aCol + 3][aRow] = bv.w;
        } else {
            *(float4*)&Bs[bRow][bCol] = bv;
        }
        __syncthreads();

        // prefetch next tile while computing this one
        Ap += 8;
        Bp += (MODE == 4) ? 8 * NCOLS : 8;
        if (k0 + 8 < K) {
            av = *(const float4*)Ap;
            bv = *(const float4*)Bp;
        }

        #pragma unroll
        for (int kk = 0; kk < 8; kk++) {
            float a[8];
            *(float4*)(a)     = *(const float4*)&As[kk][ty * 8];
            *(float4*)(a + 4) = *(const float4*)&As[kk][ty * 8 + 4];
            ulonglong2 bA = *(const ulonglong2*)&Bs[kk][tx * 8];
            ulonglong2 bB = *(const ulonglong2*)&Bs[kk][tx * 8 + 4];
            #pragma unroll
            for (int i = 0; i < 8; i++) {
                unsigned long long a2 = bcast2(a[i]);
                acc[i][0] = fma2(a2, bA.x, acc[i][0]);
                acc[i][1] = fma2(a2, bA.y, acc[i][1]);
                acc[i][2] = fma2(a2, bB.x, acc[i][2]);
                acc[i][3] = fma2(a2, bB.y, acc[i][3]);
            }
        }
        __syncthreads();
    }

    // unpack
    float cr[8][8];
    #pragma unroll
    for (int i = 0; i < 8; i++)
        #pragma unroll
        for (int jp = 0; jp < 4; jp++) {
            cr[i][2 * jp]     = __uint_as_float((unsigned)(acc[i][jp] & 0xffffffffull));
            cr[i][2 * jp + 1] = __uint_as_float((unsigned)(acc[i][jp] >> 32));
        }

    // epilogue operands
    float bias[8];
    if (MODE <= 2) {
        #pragma unroll
        for (int j = 0; j < 8; j++) bias[j] = auxf[n0 + tx * 8 + j];
    }
    int mk[8];
    if (MODE == 3) {
        const int* mrow = auxi + bz * SS + n0 + tx * 8;   // attention_mask[b,0,k]
        #pragma unroll
        for (int j = 0; j < 8; j++) mk[j] = mrow[j];
    }

    #pragma unroll
    for (int i = 0; i < 8; i++) {
        const int row = m0 + ty * 8 + i;
        float* crow = C + (size_t)row * NCOLS + n0 + tx * 8;

        if (MODE <= 2) {
            #pragma unroll
            for (int j = 0; j < 8; j++) cr[i][j] += bias[j];
        } else if (MODE == 3) {
            #pragma unroll
            for (int j = 0; j < 8; j++) {
                const int kcol = n0 + tx * 8 + j;
                float s = cr[i][j] * 0.03125f;       // 1/sqrt(1024)
                if (mk[j] == 0) s = NEGV;            // mask-replace (ref: where)
                if (kcol > row) s += NEGV;           // causal-ADD (ref semantics, fp32)
                cr[i][j] = s;
            }
        }
        *(float4*)(crow)     = *(float4*)&cr[i][0];
        *(float4*)(crow + 4) = *(float4*)&cr[i][4];
    }
}

// ---------------------------------------------------------------------------
// Row softmax over the full 2048-wide score rows (includes degenerate rows)
// ---------------------------------------------------------------------------
__global__ __launch_bounds__(256) void softmax_kernel() {
    const int row = blockIdx.x;                 // 0 .. NB*SS-1
    float* p = g_p + (size_t)row * SS;
    const int tid = threadIdx.x;

    float v[8];
    float mx = -INFINITY;
    #pragma unroll
    for (int i = 0; i < 8; i++) {
        v[i] = p[i * 256 + tid];
        mx = fmaxf(mx, v[i]);
    }
    #pragma unroll
    for (int o = 16; o > 0; o >>= 1) mx = fmaxf(mx, __shfl_xor_sync(0xffffffffu, mx, o));

    __shared__ float red[8];
    if ((tid & 31) == 0) red[tid >> 5] = mx;
    __syncthreads();
    float rmax = red[0];
    #pragma unroll
    for (int i = 1; i < 8; i++) rmax = fmaxf(rmax, red[i]);

    float s = 0.f;
    #pragma unroll
    for (int i = 0; i < 8; i++) {
        v[i] = expf(v[i] - rmax);
        s += v[i];
    }
    #pragma unroll
    for (int o = 16; o > 0; o >>= 1) s += __shfl_xor_sync(0xffffffffu, s, o);
    __syncthreads();
    if ((tid & 31) == 0) red[tid >> 5] = s;
    __syncthreads();
    float tot = 0.f;
    #pragma unroll
    for (int i = 0; i < 8; i++) tot += red[i];

    const float inv = 1.0f / tot;
    #pragma unroll
    for (int i = 0; i < 8; i++) p[i * 256 + tid] = v[i] * inv;
}

// ---------------------------------------------------------------------------
extern "C" void kernel_launch(void* const* d_in, const int* in_sizes, int n_in,
                              void* d_out, int out_size)
{
    (void)in_sizes; (void)n_in; (void)out_size;
    const float* Q    = (const float*)d_in[0];
    const float* Kin  = (const float*)d_in[1];
    const float* Vin  = (const float*)d_in[2];
    const int*   mask = (const int*)  d_in[3];
    const float* Wq   = (const float*)d_in[4];
    const float* bq   = (const float*)d_in[5];
    const float* Wk   = (const float*)d_in[6];
    const float* bk   = (const float*)d_in[7];
    const float* Wv   = (const float*)d_in[8];
    const float* bv   = (const float*)d_in[9];
    float* out = (float*)d_out;

    dim3 blk(256);
    // projections: M = NB*SS = 8192 rows, N = 1024
    gemm_kernel<0><<<dim3(8, 64, 1), blk>>>(Q,   Wq, bq, nullptr, nullptr);
    gemm_kernel<1><<<dim3(8, 64, 1), blk>>>(Kin, Wk, bk, nullptr, nullptr);
    gemm_kernel<2><<<dim3(8, 64, 1), blk>>>(Vin, Wv, bv, nullptr, nullptr);
    // scores (full S x S; degenerate masked rows require no causal skipping)
    gemm_kernel<3><<<dim3(16, 16, NB), blk>>>(nullptr, nullptr, nullptr, mask, nullptr);
    // softmax over each of NB*SS rows
    softmax_kernel<<<NB * SS, 256>>>();
    // O = P @ V
    gemm_kernel<4><<<dim3(8, 16, NB), blk>>>(nullptr, nullptr, nullptr, nullptr, out);
}

// round 3
// speedup vs baseline: 2.1884x; 2.1884x over previous
#include <cuda_runtime.h>
#include <cuda_bf16.h>
#include <cstdint>
#include <math.h>

#define NB 4
#define SS 2048
#define DD 1024
#define NEGV (-1e10f)

// ---------------------------------------------------------------------------
// Device-global scratch (allocation-free per harness rules)
// ---------------------------------------------------------------------------
__device__ __align__(128) __nv_bfloat16 g_Qh[NB*SS*DD], g_Ql[NB*SS*DD];
__device__ __align__(128) __nv_bfloat16 g_Kh[NB*SS*DD], g_Kl[NB*SS*DD];
__device__ __align__(128) __nv_bfloat16 g_Vh[NB*SS*DD], g_Vl[NB*SS*DD];
__device__ __align__(128) __nv_bfloat16 g_Wqh[DD*DD], g_Wql[DD*DD];
__device__ __align__(128) __nv_bfloat16 g_Wkh[DD*DD], g_Wkl[DD*DD];
__device__ __align__(128) __nv_bfloat16 g_Wvh[DD*DD], g_Wvl[DD*DD];
__device__ __align__(128) __nv_bfloat16 g_qh[NB*SS*DD], g_ql[NB*SS*DD];
__device__ __align__(128) __nv_bfloat16 g_kh[NB*SS*DD], g_kl[NB*SS*DD];
__device__ __align__(128) __nv_bfloat16 g_vh[NB*SS*DD], g_vl[NB*SS*DD];
__device__ __align__(128) __nv_bfloat16 g_vth[NB*DD*SS], g_vtl[NB*DD*SS]; // [b][d][s]
__device__ float         g_p[(size_t)NB*SS*SS];                           // fp32 scores
__device__ __align__(128) __nv_bfloat16 g_ph[(size_t)NB*SS*SS], g_pl[(size_t)NB*SS*SS];

// ---------------------------------------------------------------------------
// helpers
// ---------------------------------------------------------------------------
__device__ __forceinline__ uint32_t s2u(const void* p) {
    return (uint32_t)__cvta_generic_to_shared(p);
}
__device__ __forceinline__ void cp16(uint32_t dst, const void* src) {
    asm volatile("cp.async.cg.shared.global [%0], [%1], 16;\n"
                 :: "r"(dst), "l"(src) : "memory");
}
__device__ __forceinline__ void cp_commit() {
    asm volatile("cp.async.commit_group;\n" ::: "memory");
}
__device__ __forceinline__ void cp_wait2() {
    asm volatile("cp.async.wait_group 2;\n" ::: "memory");
}
__device__ __forceinline__ uint32_t ld32s(uint32_t a) {
    uint32_t v;
    asm volatile("ld.shared.b32 %0, [%1];" : "=r"(v) : "r"(a));
    return v;
}
__device__ __forceinline__ void mma16816(float* c, const uint32_t* a, const uint32_t* b) {
    asm volatile("mma.sync.aligned.m16n8k16.row.col.f32.bf16.bf16.f32 "
        "{%0,%1,%2,%3}, {%4,%5,%6,%7}, {%8,%9}, {%0,%1,%2,%3};"
        : "+f"(c[0]), "+f"(c[1]), "+f"(c[2]), "+f"(c[3])
        : "r"(a[0]), "r"(a[1]), "r"(a[2]), "r"(a[3]), "r"(b[0]), "r"(b[1]));
}
__device__ __forceinline__ uint32_t pk(__nv_bfloat16 a, __nv_bfloat16 b) {
    __nv_bfloat162 t(a, b);
    return *reinterpret_cast<uint32_t*>(&t);
}

// ---------------------------------------------------------------------------
// fp32 -> (bf16 hi, bf16 lo) split
// ---------------------------------------------------------------------------
template <int IDX>
__global__ __launch_bounds__(256) void cvt_split(const float* __restrict__ src, int n4) {
    __nv_bfloat16 *h, *l;
    if      (IDX == 0) { h = g_Qh;  l = g_Ql;  }
    else if (IDX == 1) { h = g_Kh;  l = g_Kl;  }
    else if (IDX == 2) { h = g_Vh;  l = g_Vl;  }
    else if (IDX == 3) { h = g_Wqh; l = g_Wql; }
    else if (IDX == 4) { h = g_Wkh; l = g_Wkl; }
    else               { h = g_Wvh; l = g_Wvl; }
    int i = blockIdx.x * 256 + threadIdx.x;
    if (i >= n4) return;
    float4 v = reinterpret_cast<const float4*>(src)[i];
    __nv_bfloat16 h0 = __float2bfloat16(v.x), h1 = __float2bfloat16(v.y);
    __nv_bfloat16 h2 = __float2bfloat16(v.z), h3 = __float2bfloat16(v.w);
    __nv_bfloat16 l0 = __float2bfloat16(v.x - __bfloat162float(h0));
    __nv_bfloat16 l1 = __float2bfloat16(v.y - __bfloat162float(h1));
    __nv_bfloat16 l2 = __float2bfloat16(v.z - __bfloat162float(h2));
    __nv_bfloat16 l3 = __float2bfloat16(v.w - __bfloat162float(h3));
    reinterpret_cast<uint2*>(h)[i] = make_uint2(pk(h0, h1), pk(h2, h3));
    reinterpret_cast<uint2*>(l)[i] = make_uint2(pk(l0, l1), pk(l2, l3));
}

// ---------------------------------------------------------------------------
// v [b][s][d] -> vt [b][d][s] (hi and lo)
// ---------------------------------------------------------------------------
__global__ __launch_bounds__(256) void transpose_v() {
    __shared__ __nv_bfloat16 t[64][65];
    const int b = blockIdx.z, d0 = blockIdx.x * 64, s0 = blockIdx.y * 64;
    const int tid = threadIdx.x;
    const __nv_bfloat16* srcs[2] = { g_vh, g_vl };
    __nv_bfloat16*       dsts[2] = { g_vth, g_vtl };
    for (int p = 0; p < 2; p++) {
        const __nv_bfloat16* src = srcs[p];
        __nv_bfloat16* dst = dsts[p];
        for (int i = tid; i < 64 * 64; i += 256) {
            int r = i >> 6, c = i & 63;
            t[r][c] = src[((size_t)b * SS + s0 + r) * DD + d0 + c];
        }
        __syncthreads();
        for (int i = tid; i < 64 * 64; i += 256) {
            int r = i >> 6, c = i & 63;
            dst[((size_t)b * DD + d0 + r) * SS + s0 + c] = t[c][r];
        }
        __syncthreads();
    }
}

// ---------------------------------------------------------------------------
// Split-bf16 GEMM on mma.sync (HMMA). All modes NT: C[M,N] = A[M,K] * B[N,K]^T
//  MODE 0/1/2: proj q/k/v (bias epilogue, writes hi/lo bf16)
//  MODE 3    : scores (scale+mask epilogue, writes fp32)
//  MODE 4    : PV (writes fp32 output)
// CTA tile 128x128, K-chunk 32, 3-stage cp.async pipeline, row stride 80B.
// ---------------------------------------------------------------------------
#define RSTRIDE 80
#define BUFB (128 * RSTRIDE)           // 10240 per buffer
#define STAGEB (4 * BUFB)              // Ah|Al|Bh|Bl = 40960
#define SMEM_DYN (3 * STAGEB)          // 122880

template <int MODE>
__device__ __forceinline__ void stage_cp(
    uint32_t stg, const __nv_bfloat16* Ah, const __nv_bfloat16* Al,
    const __nv_bfloat16* Bh, const __nv_bfloat16* Bl,
    int m0, int n0, int k0, int tid)
{
    constexpr int LD = (MODE == 4) ? SS : DD;
    #pragma unroll
    for (int i = 0; i < 2; i++) {
        const int idx = tid + i * 256;
        const int row = idx >> 2, seg = idx & 3;
        const uint32_t d = (uint32_t)(row * RSTRIDE + seg * 16);
        const size_t ga = (size_t)(m0 + row) * LD + k0 + seg * 8;
        const size_t gb = (size_t)(n0 + row) * LD + k0 + seg * 8;
        cp16(stg + d,            Ah + ga);
        cp16(stg + BUFB + d,     Al + ga);
        cp16(stg + 2 * BUFB + d, Bh + gb);
        cp16(stg + 3 * BUFB + d, Bl + gb);
    }
}

template <int MODE>
__global__ void __launch_bounds__(256, 1) gemm5(
    const float* __restrict__ bias, const int* __restrict__ maskp,
    float* __restrict__ outF)
{
    constexpr int KDIM = (MODE == 4) ? SS : DD;
    constexpr int NCH  = KDIM / 32;
    constexpr int NOUT = (MODE == 3) ? SS : DD;

    const int tid = threadIdx.x;
    const int wid = tid >> 5, lane = tid & 31;
    const int g = lane >> 2, t4 = lane & 3;
    const int wm = wid & 1, wn = wid >> 1;          // 2 x 4 warp grid
    const int bz = blockIdx.z;
    const int m0 = blockIdx.y * 128, n0 = blockIdx.x * 128;

    const __nv_bfloat16 *Ah, *Al, *Bh, *Bl;
    __nv_bfloat16 *oH = nullptr, *oL = nullptr;
    if      (MODE == 0) { Ah = g_Qh; Al = g_Ql; Bh = g_Wqh; Bl = g_Wql; oH = g_qh; oL = g_ql; }
    else if (MODE == 1) { Ah = g_Kh; Al = g_Kl; Bh = g_Wkh; Bl = g_Wkl; oH = g_kh; oL = g_kl; }
    else if (MODE == 2) { Ah = g_Vh; Al = g_Vl; Bh = g_Wvh; Bl = g_Wvl; oH = g_vh; oL = g_vl; }
    else if (MODE == 3) {
        Ah = g_qh + (size_t)bz * SS * DD; Al = g_ql + (size_t)bz * SS * DD;
        Bh = g_kh + (size_t)bz * SS * DD; Bl = g_kl + (size_t)bz * SS * DD;
    } else {
        Ah = g_ph + (size_t)bz * SS * SS; Al = g_pl + (size_t)bz * SS * SS;
        Bh = g_vth + (size_t)bz * DD * SS; Bl = g_vtl + (size_t)bz * DD * SS;
    }

    extern __shared__ char dsm[];
    const uint32_t sb = s2u(dsm);

    float c[4][4][4];
    #pragma unroll
    for (int mt = 0; mt < 4; mt++)
        #pragma unroll
        for (int nt = 0; nt < 4; nt++)
            #pragma unroll
            for (int i = 0; i < 4; i++) c[mt][nt][i] = 0.f;

    // prologue: stages 0, 1
    stage_cp<MODE>(sb,          Ah, Al, Bh, Bl, m0, n0, 0,  tid); cp_commit();
    stage_cp<MODE>(sb + STAGEB, Ah, Al, Bh, Bl, m0, n0, 32, tid); cp_commit();

    for (int ch = 0; ch < NCH; ch++) {
        if (ch + 2 < NCH)
            stage_cp<MODE>(sb + ((ch + 2) % 3) * STAGEB, Ah, Al, Bh, Bl,
                           m0, n0, (ch + 2) * 32, tid);
        cp_commit();
        cp_wait2();
        __syncthreads();

        const uint32_t stg = sb + (ch % 3) * STAGEB;
        const uint32_t sAh = stg, sAl = stg + BUFB;
        const uint32_t sBh = stg + 2 * BUFB, sBl = stg + 3 * BUFB;

        #pragma unroll
        for (int kk = 0; kk < 2; kk++) {
            const uint32_t kb = (uint32_t)(kk * 32 + t4 * 4);
            uint32_t ah[4][4], al[4][4], bh[4][2], bl[4][2];
            #pragma unroll
            for (int mt = 0; mt < 4; mt++) {
                const uint32_t r0 = (uint32_t)((wm * 64 + mt * 16 + g) * RSTRIDE) + kb;
                ah[mt][0] = ld32s(sAh + r0);
                ah[mt][1] = ld32s(sAh + r0 + 8 * RSTRIDE);
                ah[mt][2] = ld32s(sAh + r0 + 16);
                ah[mt][3] = ld32s(sAh + r0 + 8 * RSTRIDE + 16);
                al[mt][0] = ld32s(sAl + r0);
                al[mt][1] = ld32s(sAl + r0 + 8 * RSTRIDE);
                al[mt][2] = ld32s(sAl + r0 + 16);
                al[mt][3] = ld32s(sAl + r0 + 8 * RSTRIDE + 16);
            }
            #pragma unroll
            for (int nt = 0; nt < 4; nt++) {
                const uint32_t r0 = (uint32_t)((wn * 32 + nt * 8 + g) * RSTRIDE) + kb;
                bh[nt][0] = ld32s(sBh + r0);
                bh[nt][1] = ld32s(sBh + r0 + 16);
                bl[nt][0] = ld32s(sBl + r0);
                bl[nt][1] = ld32s(sBl + r0 + 16);
            }
            #pragma unroll
            for (int mt = 0; mt < 4; mt++)
                #pragma unroll
                for (int nt = 0; nt < 4; nt++) {
                    mma16816(c[mt][nt], ah[mt], bh[nt]);   // hh
                    mma16816(c[mt][nt], ah[mt], bl[nt]);   // hl
                    mma16816(c[mt][nt], al[mt], bh[nt]);   // lh
                }
        }
        __syncthreads();
    }

    // ---- epilogue ----
    #pragma unroll
    for (int mt = 0; mt < 4; mt++) {
        #pragma unroll
        for (int half = 0; half < 2; half++) {
            const int row = m0 + wm * 64 + mt * 16 + g + half * 8;
            #pragma unroll
            for (int nt = 0; nt < 4; nt++) {
                const int cb = n0 + wn * 32 + nt * 8 + t4 * 2;
                float v0 = c[mt][nt][half * 2];
                float v1 = c[mt][nt][half * 2 + 1];
                if (MODE <= 2) {
                    v0 += bias[cb]; v1 += bias[cb + 1];
                    __nv_bfloat16 h0 = __float2bfloat16(v0), h1 = __float2bfloat16(v1);
                    __nv_bfloat16 l0 = __float2bfloat16(v0 - __bfloat162float(h0));
                    __nv_bfloat16 l1 = __float2bfloat16(v1 - __bfloat162float(h1));
                    *reinterpret_cast<uint32_t*>(oH + (size_t)row * DD + cb) = pk(h0, h1);
                    *reinterpret_cast<uint32_t*>(oL + (size_t)row * DD + cb) = pk(l0, l1);
                } else if (MODE == 3) {
                    const int* mrow = maskp + bz * SS;
                    float s0 = v0 * 0.03125f, s1 = v1 * 0.03125f;
                    if (mrow[cb] == 0)     s0 = NEGV;
                    if (mrow[cb + 1] == 0) s1 = NEGV;
                    // rowL is the per-batch row for causal compare
                    const int rowL = row;  // m0 is per-batch for MODE 3
                    if (cb > rowL)     s0 += NEGV;
                    if (cb + 1 > rowL) s1 += NEGV;
                    float2 st = make_float2(s0, s1);
                    *reinterpret_cast<float2*>(g_p + (size_t)bz * SS * SS +
                                               (size_t)rowL * SS + cb) = st;
                } else {
                    float2 st = make_float2(v0, v1);
                    *reinterpret_cast<float2*>(outF + ((size_t)bz * SS + row) * NOUT + cb) = st;
                }
            }
        }
    }
}

// ---------------------------------------------------------------------------
// Row softmax (fp32 in, split-bf16 out)
// ---------------------------------------------------------------------------
__global__ __launch_bounds__(256) void softmax_kernel() {
    const int row = blockIdx.x;
    const float* p = g_p + (size_t)row * SS;
    __nv_bfloat16* ph = g_ph + (size_t)row * SS;
    __nv_bfloat16* pl = g_pl + (size_t)row * SS;
    const int tid = threadIdx.x;

    float v[8];
    float mx = -INFINITY;
    #pragma unroll
    for (int i = 0; i < 8; i++) { v[i] = p[i * 256 + tid]; mx = fmaxf(mx, v[i]); }
    #pragma unroll
    for (int o = 16; o > 0; o >>= 1) mx = fmaxf(mx, __shfl_xor_sync(0xffffffffu, mx, o));

    __shared__ float red[8];
    if ((tid & 31) == 0) red[tid >> 5] = mx;
    __syncthreads();
    float rmax = red[0];
    #pragma unroll
    for (int i = 1; i < 8; i++) rmax = fmaxf(rmax, red[i]);

    float s = 0.f;
    #pragma unroll
    for (int i = 0; i < 8; i++) { v[i] = expf(v[i] - rmax); s += v[i]; }
    #pragma unroll
    for (int o = 16; o > 0; o >>= 1) s += __shfl_xor_sync(0xffffffffu, s, o);
    __syncthreads();
    if ((tid & 31) == 0) red[tid >> 5] = s;
    __syncthreads();
    float tot = 0.f;
    #pragma unroll
    for (int i = 0; i < 8; i++) tot += red[i];

    const float inv = 1.0f / tot;
    #pragma unroll
    for (int i = 0; i < 8; i++) {
        float w = v[i] * inv;
        __nv_bfloat16 h = __float2bfloat16(w);
        __nv_bfloat16 l = __float2bfloat16(w - __bfloat162float(h));
        ph[i * 256 + tid] = h;
        pl[i * 256 + tid] = l;
    }
}

// ---------------------------------------------------------------------------
extern "C" void kernel_launch(void* const* d_in, const int* in_sizes, int n_in,
                              void* d_out, int out_size)
{
    (void)in_sizes; (void)n_in; (void)out_size;
    const float* Q    = (const float*)d_in[0];
    const float* Kin  = (const float*)d_in[1];
    const float* Vin  = (const float*)d_in[2];
    const int*   mask = (const int*)  d_in[3];
    const float* Wq   = (const float*)d_in[4];
    const float* bq   = (const float*)d_in[5];
    const float* Wk   = (const float*)d_in[6];
    const float* bk   = (const float*)d_in[7];
    const float* Wv   = (const float*)d_in[8];
    const float* bv   = (const float*)d_in[9];
    float* out = (float*)d_out;

    cudaFuncSetAttribute(gemm5<0>, cudaFuncAttributeMaxDynamicSharedMemorySize, SMEM_DYN);
    cudaFuncSetAttribute(gemm5<1>, cudaFuncAttributeMaxDynamicSharedMemorySize, SMEM_DYN);
    cudaFuncSetAttribute(gemm5<2>, cudaFuncAttributeMaxDynamicSharedMemorySize, SMEM_DYN);
    cudaFuncSetAttribute(gemm5<3>, cudaFuncAttributeMaxDynamicSharedMemorySize, SMEM_DYN);
    cudaFuncSetAttribute(gemm5<4>, cudaFuncAttributeMaxDynamicSharedMemorySize, SMEM_DYN);

    const int nBig4 = NB * SS * DD / 4;
    const int nW4   = DD * DD / 4;
    cvt_split<0><<<nBig4 / 256, 256>>>(Q,   nBig4);
    cvt_split<1><<<nBig4 / 256, 256>>>(Kin, nBig4);
    cvt_split<2><<<nBig4 / 256, 256>>>(Vin, nBig4);
    cvt_split<3><<<nW4 / 256, 256>>>(Wq, nW4);
    cvt_split<4><<<nW4 / 256, 256>>>(Wk, nW4);
    cvt_split<5><<<nW4 / 256, 256>>>(Wv, nW4);

    // projections: M = 8192 (batch-flat), N = 1024
    gemm5<0><<<dim3(8, 64, 1), 256, SMEM_DYN>>>(bq, nullptr, nullptr);
    gemm5<1><<<dim3(8, 64, 1), 256, SMEM_DYN>>>(bk, nullptr, nullptr);
    gemm5<2><<<dim3(8, 64, 1), 256, SMEM_DYN>>>(bv, nullptr, nullptr);

    transpose_v<<<dim3(16, 32, NB), 256>>>();

    // scores: per-batch 2048 x 2048, K = 1024
    gemm5<3><<<dim3(16, 16, NB), 256, SMEM_DYN>>>(nullptr, mask, nullptr);

    softmax_kernel<<<NB * SS, 256>>>();

    // O = P @ V : per-batch 2048 x 1024, K = 2048
    gemm5<4><<<dim3(8, 16, NB), 256, SMEM_DYN>>>(nullptr, nullptr, out);
}